// round 8
// baseline (speedup 1.0000x reference)
#include <cuda_runtime.h>
#include <cuda_fp16.h>

namespace {

constexpr int Bsz = 32768;
constexpr int NIN = 41;
constexpr int WPB = 8;     // warps per block; each warp handles 2 elements
constexpr unsigned FULL = 0xffffffffu;

__device__ __forceinline__ float clamp1(float w) {
    return fminf(fmaxf(w, -1.f), 1.f);
}
__device__ __forceinline__ float clipv(float w) {
    return fminf(fmaxf(w, -0.2f), 1.0f);
}
__device__ __forceinline__ float blurcoef(int x, int y) {
    int d = x - y; if (d < 0) d = -d;
    return (d == 0) ? 0.8f : (d == 1 ? 0.1f : 0.f);
}

__global__ __launch_bounds__(WPB * 32, 2) void pgnet_kernel(
    const float* __restrict__ inp,
    const float* __restrict__ fpg_w,
    const float* __restrict__ fpg_b,
    const float* __restrict__ rpg_w,
    const float* __restrict__ rpg_b,
    const float* __restrict__ pgctrl_w,
    const float* __restrict__ pgctrl_b,
    float* __restrict__ out)
{
    __shared__ float s_wsum[8][44];
    __shared__ float s_wc2[8][44];
    __shared__ float s_pb[8];
    __shared__ float s_B3[8][9];
    __shared__ float s_B2[4][5];
    __shared__ float s_inp[WPB * 2][44];
    __shared__ float s_rb[WPB * 2][44];

    const int tid  = threadIdx.x;
    const int warp = tid >> 5;
    const int lane = tid & 31;
    const int b0 = (blockIdx.x * WPB + warp) * 2;   // elements b0, b0+1
    const int q   = lane >> 3;     // 0..3
    const int j   = lane & 7;      // 0..7
    const int j2  = j >> 2;
    const int j01 = j & 3;

    const float4* rw4[2] = {
        (const float4*)(rpg_w + (long)b0 * 1312),
        (const float4*)(rpg_w + (long)(b0 + 1) * 1312) };
    const float4* fw4[2] = {
        (const float4*)(fpg_w + (long)b0 * 1312),
        (const float4*)(fpg_w + (long)(b0 + 1) * 1312) };

    // ---- per-warp input vectors (both elements) ----
    #pragma unroll
    for (int e = 0; e < 2; e++) {
        int be = b0 + e;
        int row = warp * 2 + e;
        if (lane < NIN)      { s_inp[row][lane]      = inp[be * NIN + lane];
                               s_rb[row][lane]       = rpg_b[be * NIN + lane]; }
        if (lane + 32 < NIN) { s_inp[row][lane + 32] = inp[be * NIN + lane + 32];
                               s_rb[row][lane + 32]  = rpg_b[be * NIN + lane + 32]; }
        if (lane >= 9 && lane < 12) s_rb[row][lane + 32] = 0.f;
    }

    // ---- block-shared pgctrl tables + blur powers ----
    for (int idx = tid; idx < 8 * 44; idx += WPB * 32) {
        int rr = idx / 44, oo = idx % 44;
        float w2 = (oo < NIN) ? pgctrl_w[rr * 86 + 45 + oo] : 0.f;
        s_wc2[rr][oo]  = w2;
        s_wsum[rr][oo] = (oo < NIN) ? (pgctrl_w[rr * 86 + oo] + w2) : 0.f;
    }
    if (tid < 8) s_pb[tid] = pgctrl_b[tid];
    if (tid < 64) {
        int r0 = tid >> 3, c0 = tid & 7;
        float acc = 0.f;
        #pragma unroll
        for (int k = 0; k < 8; k++)
            #pragma unroll
            for (int m = 0; m < 8; m++)
                acc += blurcoef(r0, k) * blurcoef(k, m) * blurcoef(m, c0);
        s_B3[r0][c0] = acc;
    }
    if (tid >= 64 && tid < 80) {
        int t = tid - 64, r0 = t >> 2, c0 = t & 3;
        float acc = 0.f;
        #pragma unroll
        for (int k = 0; k < 4; k++)
            acc += blurcoef(r0, k) * blurcoef(k, c0);
        s_B2[r0][c0] = acc;
    }

    float fb[2];
    #pragma unroll
    for (int e = 0; e < 2; e++) fb[e] = fpg_b[(b0 + e) * 4 + q];

    __syncthreads();

    const float* si[2] = { s_inp[warp * 2], s_inp[warp * 2 + 1] };

    // ---- fpg dot, direct from global, both elements interleaved ----
    // float4 n = q*82 + 2k + j2 -> (o=q, k, r = 4*j2 + 0..3)
    float fa[2][4];
    #pragma unroll
    for (int e = 0; e < 2; e++)
        #pragma unroll
        for (int t = 0; t < 4; t++) fa[e][t] = 0.f;
    #pragma unroll
    for (int m = 0; m < 11; m++) {
        int k = j01 + 4 * m;
        if (k <= 40) {
            #pragma unroll
            for (int e = 0; e < 2; e++) {
                float4 g = __ldcs(&fw4[e][q * 82 + 2 * k + j2]);
                float x = si[e][k];
                fa[e][0] = fmaf(clamp1(g.x), x, fa[e][0]);
                fa[e][1] = fmaf(clamp1(g.y), x, fa[e][1]);
                fa[e][2] = fmaf(clamp1(g.z), x, fa[e][2]);
                fa[e][3] = fmaf(clamp1(g.w), x, fa[e][3]);
            }
        }
    }
    float fdot[2];
    #pragma unroll
    for (int e = 0; e < 2; e++) {
        #pragma unroll
        for (int t = 0; t < 4; t++) {
            fa[e][t] += __shfl_xor_sync(FULL, fa[e][t], 1);
            fa[e][t] += __shfl_xor_sync(FULL, fa[e][t], 2);
        }
        float f01 = (j & 1) ? fa[e][1] : fa[e][0];
        float f23 = (j & 1) ? fa[e][3] : fa[e][2];
        fdot[e] = (j & 2) ? f23 : f01;
    }

    // ---- rpg_w: coalesced direct-to-register loads, both elements ----
    // float4 n = 32m + 8q + 2*j01 + j2 -> (o = 4m+q, i = j01, r = 4*j2 + 0..3)
    __half2 wh[2][22];
    #pragma unroll
    for (int m = 0; m < 11; m++) {
        int o = 4 * m + q;
        #pragma unroll
        for (int e = 0; e < 2; e++) {
            float4 f;
            if (o < NIN) f = __ldcs(&rw4[e][32 * m + 8 * q + 2 * j01 + j2]);
            else         f = make_float4(0.f, 0.f, 0.f, 0.f);
            wh[e][2 * m]     = __floats2half2_rn(clamp1(f.x), clamp1(f.y));
            wh[e][2 * m + 1] = __floats2half2_rn(clamp1(f.z), clamp1(f.w));
        }
    }

    // ---- A_j: iteration-invariant rc preactivation ----
    float A[2];
    #pragma unroll
    for (int e = 0; e < 2; e++) {
        float a = s_pb[j];
        #pragma unroll
        for (int i = 0; i < NIN; i++) a = fmaf(si[e][i], s_wsum[j][i], a);
        A[e] = a;
    }

    float l1i[2][11];
    #pragma unroll
    for (int e = 0; e < 2; e++)
        #pragma unroll
        for (int s = 0; s < 11; s++) l1i[e][s] = 0.f;
    float rc[2] = {0.f, 0.f}, l2v[2] = {0.f, 0.f};

    #pragma unroll
    for (int it = 0; it < 2; it++) {
        float v[2];
        #pragma unroll
        for (int e = 0; e < 2; e++) {
            float D = 0.f;
            if (it > 0) {
                #pragma unroll
                for (int s = 0; s < 11; s++)
                    D = fmaf(l1i[e][s], s_wc2[j][4 * s + q], D);
                D += __shfl_xor_sync(FULL, D, 8);
                D += __shfl_xor_sync(FULL, D, 16);
            }
            float x = A[e] - D;
            x = (x >= 0.f) ? x : 0.2f * x;
            v[e] = clipv(0.4f * x);
        }

        float rcg[2][4];
        #pragma unroll
        for (int e = 0; e < 2; e++) {
            float vv[8];
            #pragma unroll
            for (int k = 0; k < 8; k++)
                vv[k] = __shfl_sync(FULL, v[e], (lane & 24) | k);
            float acc = 0.f;
            #pragma unroll
            for (int m = 0; m < 8; m++) acc = fmaf(s_B3[j][m], vv[m], acc);
            rc[e] = acc;
            #pragma unroll
            for (int t = 0; t < 4; t++) {
                float a2 = 0.f;
                #pragma unroll
                for (int m = 0; m < 8; m++)
                    a2 = fmaf(s_B3[4 * j2 + t][m], vv[m], a2);
                rcg[e][t] = a2;
            }
        }

        float pp[2][4];
        #pragma unroll
        for (int e = 0; e < 2; e++) {
            float acc = fdot[e] * rc[e];
            acc += __shfl_xor_sync(FULL, acc, 1);
            acc += __shfl_xor_sync(FULL, acc, 2);
            acc += __shfl_xor_sync(FULL, acc, 4);
            float t2 = clipv(0.1f * (acc + fb[e]));
            float t2a = __shfl_xor_sync(FULL, t2, 8);
            float t2b = __shfl_xor_sync(FULL, t2, 16);
            float t2c = __shfl_xor_sync(FULL, t2, 24);
            float tq[4];
            tq[q] = t2; tq[q ^ 1] = t2a; tq[q ^ 2] = t2b; tq[q ^ 3] = t2c;
            float l2all[4];
            #pragma unroll
            for (int i = 0; i < 4; i++) {
                float a2v = 0.f;
                #pragma unroll
                for (int m = 0; m < 4; m++) a2v = fmaf(s_B2[i][m], tq[m], a2v);
                l2all[i] = a2v;
            }
            l2v[e] = l2all[q];
            float l01 = (j & 1) ? l2all[1] : l2all[0];
            float l23 = (j & 1) ? l2all[3] : l2all[2];
            float l2i = (j & 2) ? l23 : l01;
            #pragma unroll
            for (int t = 0; t < 4; t++) pp[e][t] = l2i * rcg[e][t];
        }

        #pragma unroll
        for (int s = 0; s < 11; s++) {
            float a[2];
            #pragma unroll
            for (int e = 0; e < 2; e++) {
                float2 w01 = __half22float2(wh[e][2 * s]);
                float2 w23 = __half22float2(wh[e][2 * s + 1]);
                float t = w01.x * pp[e][0];
                t = fmaf(w01.y, pp[e][1], t);
                t = fmaf(w23.x, pp[e][2], t);
                t = fmaf(w23.y, pp[e][3], t);
                a[e] = t;
            }
            // interleave the two butterfly chains
            a[0] += __shfl_xor_sync(FULL, a[0], 1);
            a[1] += __shfl_xor_sync(FULL, a[1], 1);
            a[0] += __shfl_xor_sync(FULL, a[0], 2);
            a[1] += __shfl_xor_sync(FULL, a[1], 2);
            a[0] += __shfl_xor_sync(FULL, a[0], 4);
            a[1] += __shfl_xor_sync(FULL, a[1], 4);
            #pragma unroll
            for (int e = 0; e < 2; e++)
                l1i[e][s] = clipv(a[e] + s_rb[warp * 2 + e][4 * s + q]);
        }
    }

    // ---- outputs: concat(l1i [B,41], l2 [B,4], rc [B,8]) ----
    #pragma unroll
    for (int e = 0; e < 2; e++) {
        int be = b0 + e;
        if (j == 0) {
            #pragma unroll
            for (int s = 0; s < 11; s++) {
                int o = 4 * s + q;
                if (o < NIN) out[(long)be * NIN + o] = l1i[e][s];
            }
            out[(long)Bsz * NIN + be * 4 + q] = l2v[e];
        }
        if (lane < 8)
            out[(long)Bsz * 45 + be * 8 + lane] = rc[e];
    }
}

} // namespace

extern "C" void kernel_launch(void* const* d_in, const int* in_sizes, int n_in,
                              void* d_out, int out_size) {
    pgnet_kernel<<<Bsz / (WPB * 2), WPB * 32>>>(
        (const float*)d_in[0],   // inp
        (const float*)d_in[1],   // fpg_w
        (const float*)d_in[2],   // fpg_b
        (const float*)d_in[3],   // rpg_w
        (const float*)d_in[4],   // rpg_b
        (const float*)d_in[5],   // pgctrl_w
        (const float*)d_in[6],   // pgctrl_b
        (float*)d_out);
}

// round 9
// speedup vs baseline: 1.0447x; 1.0447x over previous
#include <cuda_runtime.h>
#include <cuda_fp16.h>
#include <cstdint>

namespace {

constexpr int Bsz = 32768;
constexpr int NIN = 41;
constexpr int NW  = 4;                         // warps per CTA
constexpr int EPW = 4;                         // stages (elements per warp)
constexpr int ELEM_F = 1312;                   // floats per element per tensor
constexpr int STAGE_F = NW * 2 * ELEM_F;       // 10496 floats per stage
constexpr unsigned STAGE_BYTES = STAGE_F * 4;  // 41984
constexpr unsigned BLK_BYTES = NW * ELEM_F * 4; // 20992 per tensor per stage
constexpr unsigned FULL = 0xffffffffu;

__device__ __forceinline__ float clamp1(float w) {
    return fminf(fmaxf(w, -1.f), 1.f);
}
__device__ __forceinline__ float clipv(float w) {
    return fminf(fmaxf(w, -0.2f), 1.0f);
}
__device__ __forceinline__ float blurcoef(int x, int y) {
    int d = x - y; if (d < 0) d = -d;
    return (d == 0) ? 0.8f : (d == 1 ? 0.1f : 0.f);
}
__device__ __forceinline__ uint32_t smem_u32(const void* p) {
    uint32_t a;
    asm("{ .reg .u64 t; cvta.to.shared.u64 t, %1; cvt.u32.u64 %0, t; }"
        : "=r"(a) : "l"(p));
    return a;
}
__device__ __forceinline__ void mbar_init(uint32_t mbar, uint32_t cnt) {
    asm volatile("mbarrier.init.shared.b64 [%0], %1;" :: "r"(mbar), "r"(cnt) : "memory");
}
__device__ __forceinline__ void mbar_expect_tx(uint32_t mbar, uint32_t bytes) {
    asm volatile("mbarrier.arrive.expect_tx.shared.b64 _, [%0], %1;"
                 :: "r"(mbar), "r"(bytes) : "memory");
}
__device__ __forceinline__ void bulk_g2s(uint32_t dst, const void* src,
                                         uint32_t bytes, uint32_t mbar) {
    asm volatile(
        "cp.async.bulk.shared::cta.global.mbarrier::complete_tx::bytes "
        "[%0], [%1], %2, [%3];"
        :: "r"(dst), "l"(src), "r"(bytes), "r"(mbar) : "memory");
}
__device__ __forceinline__ void mbar_wait(uint32_t mbar, uint32_t parity) {
    asm volatile(
        "{\n\t.reg .pred P;\n\t"
        "WAIT_%=:\n\t"
        "mbarrier.try_wait.parity.shared.b64 P, [%0], %1;\n\t"
        "@!P bra WAIT_%=;\n\t}"
        :: "r"(mbar), "r"(parity) : "memory");
}

__global__ __launch_bounds__(NW * 32) void pgnet_kernel(
    const float* __restrict__ inp,
    const float* __restrict__ fpg_w,
    const float* __restrict__ fpg_b,
    const float* __restrict__ rpg_w,
    const float* __restrict__ rpg_b,
    const float* __restrict__ pgctrl_w,
    const float* __restrict__ pgctrl_b,
    float* __restrict__ out)
{
    extern __shared__ float dynf[];   // [2][STAGE_F]: [fpg x4 elems][rpg x4 elems]

    __shared__ float s_wsum[8][44];
    __shared__ float s_wc2[8][44];
    __shared__ float s_pb[8];
    __shared__ float s_B3[8][9];
    __shared__ float s_B2[4][5];
    __shared__ float s_inp[NW][44];
    __shared__ float s_rb[NW][44];
    __shared__ __align__(8) unsigned long long s_mbar[2];

    const int tid  = threadIdx.x;
    const int warp = tid >> 5;
    const int lane = tid & 31;
    const int cbase = blockIdx.x * (NW * EPW);
    const int q   = lane >> 3;
    const int j   = lane & 7;
    const int j2  = j >> 2;
    const int j01 = j & 3;

    // ---- block-shared pgctrl tables + blur powers ----
    for (int idx = tid; idx < 8 * 44; idx += NW * 32) {
        int rr = idx / 44, oo = idx % 44;
        float w2 = (oo < NIN) ? pgctrl_w[rr * 86 + 45 + oo] : 0.f;
        s_wc2[rr][oo]  = w2;
        s_wsum[rr][oo] = (oo < NIN) ? (pgctrl_w[rr * 86 + oo] + w2) : 0.f;
    }
    if (tid < 8) s_pb[tid] = pgctrl_b[tid];
    if (tid < 64) {
        int r0 = tid >> 3, c0 = tid & 7;
        float acc = 0.f;
        #pragma unroll
        for (int k = 0; k < 8; k++)
            #pragma unroll
            for (int m = 0; m < 8; m++)
                acc += blurcoef(r0, k) * blurcoef(k, m) * blurcoef(m, c0);
        s_B3[r0][c0] = acc;
    }
    if (tid >= 64 && tid < 80) {
        int t = tid - 64, r0 = t >> 2, c0 = t & 3;
        float acc = 0.f;
        #pragma unroll
        for (int k = 0; k < 4; k++)
            acc += blurcoef(r0, k) * blurcoef(k, c0);
        s_B2[r0][c0] = acc;
    }

    const uint32_t mb0 = smem_u32(&s_mbar[0]);
    const uint32_t dynb = smem_u32(dynf);
    if (tid == 0) {
        mbar_init(mb0, 1);
        mbar_init(mb0 + 8, 1);
    }
    __syncthreads();

    // ---- prologue: issue stages 0 and 1 ----
    if (tid == 0) {
        #pragma unroll
        for (int st = 0; st < 2; st++) {
            uint32_t mb = mb0 + (st & 1) * 8;
            uint32_t buf = dynb + (st & 1) * STAGE_BYTES;
            long e0 = cbase + st * NW;
            mbar_expect_tx(mb, STAGE_BYTES);
            bulk_g2s(buf,             fpg_w + e0 * ELEM_F, BLK_BYTES, mb);
            bulk_g2s(buf + BLK_BYTES, rpg_w + e0 * ELEM_F, BLK_BYTES, mb);
        }
    }

    for (int s = 0; s < EPW; s++) {
        const int be = cbase + s * NW + warp;

        // ---- small per-element loads (independent of pipeline) ----
        if (lane < NIN)      { s_inp[warp][lane]      = inp[be * NIN + lane];
                               s_rb[warp][lane]       = rpg_b[be * NIN + lane]; }
        if (lane + 32 < NIN) { s_inp[warp][lane + 32] = inp[be * NIN + lane + 32];
                               s_rb[warp][lane + 32]  = rpg_b[be * NIN + lane + 32]; }
        if (lane >= 9 && lane < 12) s_rb[warp][lane + 32] = 0.f;
        const float fb = fpg_b[be * 4 + q];
        __syncwarp();

        // ---- wait for this stage's weights ----
        mbar_wait(mb0 + (s & 1) * 8, (s >> 1) & 1);

        const float* sf = dynf + (s & 1) * STAGE_F + warp * ELEM_F;
        const float* sr = dynf + (s & 1) * STAGE_F + NW * ELEM_F + warp * ELEM_F;
        const float* si = s_inp[warp];

        // ---- hoisted fpg dot: fdot(o=q, r=j), conflict-free scalar LDS ----
        float fdot = 0.f;
        #pragma unroll
        for (int k = 0; k < NIN; k++)
            fdot = fmaf(clamp1(sf[q * 328 + k * 8 + j]), si[k], fdot);

        // ---- rpg weights -> half2 regs (conflict-free LDS.128, once) ----
        __half2 wh[22];
        #pragma unroll
        for (int m = 0; m < 11; m++) {
            int o = 4 * m + q;
            float4 f;
            if (o < NIN) f = *(const float4*)(sr + o * 32 + j01 * 8 + 4 * j2);
            else         f = make_float4(0.f, 0.f, 0.f, 0.f);
            wh[2 * m]     = __floats2half2_rn(clamp1(f.x), clamp1(f.y));
            wh[2 * m + 1] = __floats2half2_rn(clamp1(f.z), clamp1(f.w));
        }

        // ---- A_j: iteration-invariant rc preactivation ----
        float A = s_pb[j];
        #pragma unroll
        for (int i = 0; i < NIN; i++) A = fmaf(si[i], s_wsum[j][i], A);

        float l1i[11];
        #pragma unroll
        for (int t = 0; t < 11; t++) l1i[t] = 0.f;
        float rc = 0.f, l2v = 0.f;

        #pragma unroll
        for (int it = 0; it < 2; it++) {
            float D = 0.f;
            if (it > 0) {
                #pragma unroll
                for (int t = 0; t < 11; t++)
                    D = fmaf(l1i[t], s_wc2[j][4 * t + q], D);
                D += __shfl_xor_sync(FULL, D, 8);
                D += __shfl_xor_sync(FULL, D, 16);
            }

            float x = A - D;
            x = (x >= 0.f) ? x : 0.2f * x;
            float v = clipv(0.4f * x);

            float vv[8];
            #pragma unroll
            for (int k = 0; k < 8; k++)
                vv[k] = __shfl_sync(FULL, v, (lane & 24) | k);
            {
                float acc = 0.f;
                #pragma unroll
                for (int m = 0; m < 8; m++) acc = fmaf(s_B3[j][m], vv[m], acc);
                rc = acc;
            }
            float rcg[4];
            #pragma unroll
            for (int t = 0; t < 4; t++)
                rcg[t] = __shfl_sync(FULL, rc, (lane & 24) | (4 * j2 + t));

            // ---- fpg -> l2: scale + 8-lane reduce + dense blur^2 ----
            float acc = fdot * rc;
            acc += __shfl_xor_sync(FULL, acc, 1);
            acc += __shfl_xor_sync(FULL, acc, 2);
            acc += __shfl_xor_sync(FULL, acc, 4);
            float t2 = clipv(0.1f * (acc + fb));
            float t2a = __shfl_xor_sync(FULL, t2, 8);
            float t2b = __shfl_xor_sync(FULL, t2, 16);
            float t2c = __shfl_xor_sync(FULL, t2, 24);
            float tq[4];
            tq[q] = t2; tq[q ^ 1] = t2a; tq[q ^ 2] = t2b; tq[q ^ 3] = t2c;
            float l2all[4];
            #pragma unroll
            for (int i = 0; i < 4; i++) {
                float a2v = 0.f;
                #pragma unroll
                for (int m = 0; m < 4; m++) a2v = fmaf(s_B2[i][m], tq[m], a2v);
                l2all[i] = a2v;
            }
            l2v = l2all[q];

            float l01 = (j & 1) ? l2all[1] : l2all[0];
            float l23 = (j & 1) ? l2all[3] : l2all[2];
            float l2i = (j & 2) ? l23 : l01;
            float pp0 = l2i * rcg[0];
            float pp1 = l2i * rcg[1];
            float pp2 = l2i * rcg[2];
            float pp3 = l2i * rcg[3];

            // ---- rpg -> l1i: lane slice (o=4t+q, i=j01, r=4*j2+..) ----
            #pragma unroll
            for (int t = 0; t < 11; t++) {
                float2 w01 = __half22float2(wh[2 * t]);
                float2 w23 = __half22float2(wh[2 * t + 1]);
                float a = w01.x * pp0;
                a = fmaf(w01.y, pp1, a);
                a = fmaf(w23.x, pp2, a);
                a = fmaf(w23.y, pp3, a);
                a += __shfl_xor_sync(FULL, a, 1);
                a += __shfl_xor_sync(FULL, a, 2);
                a += __shfl_xor_sync(FULL, a, 4);
                l1i[t] = clipv(a + s_rb[warp][4 * t + q]);
            }
        }

        // ---- outputs: concat(l1i [B,41], l2 [B,4], rc [B,8]) ----
        if (j == 0) {
            #pragma unroll
            for (int t = 0; t < 11; t++) {
                int o = 4 * t + q;
                if (o < NIN) out[(long)be * NIN + o] = l1i[t];
            }
            out[(long)Bsz * NIN + be * 4 + q] = l2v;
        }
        if (lane < 8)
            out[(long)Bsz * 45 + be * 8 + lane] = rc;

        // ---- buffer free; issue stage s+2 into it ----
        __syncthreads();
        if (tid == 0 && s + 2 < EPW) {
            int st = s + 2;
            uint32_t mb = mb0 + (st & 1) * 8;
            uint32_t buf = dynb + (st & 1) * STAGE_BYTES;
            long e0 = cbase + st * NW;
            mbar_expect_tx(mb, STAGE_BYTES);
            bulk_g2s(buf,             fpg_w + e0 * ELEM_F, BLK_BYTES, mb);
            bulk_g2s(buf + BLK_BYTES, rpg_w + e0 * ELEM_F, BLK_BYTES, mb);
        }
    }
}

} // namespace

extern "C" void kernel_launch(void* const* d_in, const int* in_sizes, int n_in,
                              void* d_out, int out_size) {
    cudaFuncSetAttribute(pgnet_kernel,
                         cudaFuncAttributeMaxDynamicSharedMemorySize,
                         2 * (int)STAGE_BYTES);
    pgnet_kernel<<<Bsz / (NW * EPW), NW * 32, 2 * STAGE_BYTES>>>(
        (const float*)d_in[0],   // inp
        (const float*)d_in[1],   // fpg_w
        (const float*)d_in[2],   // fpg_b
        (const float*)d_in[3],   // rpg_w
        (const float*)d_in[4],   // rpg_b
        (const float*)d_in[5],   // pgctrl_w
        (const float*)d_in[6],   // pgctrl_b
        (float*)d_out);
}